// round 11
// baseline (speedup 1.0000x reference)
#include <cuda_runtime.h>
#include <cuda_fp16.h>
#include <cstdint>

// ---------------------------------------------------------------------------
// Problem constants
// ---------------------------------------------------------------------------
#define B_TOK 16384
#define K_TOP 2
#define E_EXP 64
#define H_DIM 512
#define F_DIM 1024
#define N_ASG 32768            // B*K assignments
#define CAP   512              // per-expert (balanced routing)

#define NCHUNK 8
#define NE_CHUNK (E_EXP / NCHUNK)   // 8 experts per chunk

// GEMM tiling: CTA 128x128, 8 warps (2Mx4N, 64x32 each), K-stage 64, 3 stages
#define STAGES 3
#define TILE_ROW_BYTES 128                       // 64 halves, XOR-swizzled 16B chunks
#define A_SM_BYTES (128 * TILE_ROW_BYTES)        // 16384
#define STAGE_BYTES (2 * A_SM_BYTES)             // 32768 (A + B)
#define DYN_SMEM (STAGES * STAGE_BYTES)          // 98304 -> 2 CTAs/SM

// ---------------------------------------------------------------------------
// Scratch (device globals)
// ---------------------------------------------------------------------------
__device__ int    d_cnt[E_EXP];
__device__ int    d_slot[N_ASG];    // [e*CAP + p] = assignment n
__device__ __half d_xh [(size_t)B_TOK * H_DIM];          //  17 MB hidden fp16
__device__ __half d_w1h[(size_t)E_EXP * F_DIM * H_DIM];  //  67 MB W1^T  [e][f][h]
__device__ __half d_w2h[(size_t)E_EXP * H_DIM * F_DIM];  //  67 MB W2^T  [e][h][f]
__device__ __half d_hidh[(size_t)N_ASG * F_DIM];         //  67 MB silu(x@W1) fp16
__device__ __half d_yw [(size_t)N_ASG * H_DIM];          //  34 MB weighted outputs fp16, n-indexed

// ---------------------------------------------------------------------------
// PTX helpers (sm_80-vintage, base-sm_100 legal)
// ---------------------------------------------------------------------------
__device__ __forceinline__ uint32_t smem_u32(const void* p) {
    uint32_t a;
    asm("{ .reg .u64 t; cvta.to.shared.u64 t, %1; cvt.u32.u64 %0, t; }" : "=r"(a) : "l"(p));
    return a;
}
__device__ __forceinline__ void cp16(uint32_t dst, const void* src) {
    asm volatile("cp.async.cg.shared.global [%0], [%1], 16;" :: "r"(dst), "l"(src));
}
#define CP_COMMIT() asm volatile("cp.async.commit_group;" ::: "memory")
#define CP_WAIT1()  asm volatile("cp.async.wait_group 1;" ::: "memory")

__device__ __forceinline__ void ldsm_x4(uint32_t* r, uint32_t addr) {
    asm volatile("ldmatrix.sync.aligned.m8n8.x4.shared.b16 {%0,%1,%2,%3}, [%4];"
                 : "=r"(r[0]), "=r"(r[1]), "=r"(r[2]), "=r"(r[3]) : "r"(addr));
}
__device__ __forceinline__ void mma_f16(float* c, const uint32_t* a, const uint32_t* b) {
    asm volatile(
        "mma.sync.aligned.m16n8k16.row.col.f32.f16.f16.f32 "
        "{%0,%1,%2,%3}, {%4,%5,%6,%7}, {%8,%9}, {%0,%1,%2,%3};"
        : "+f"(c[0]), "+f"(c[1]), "+f"(c[2]), "+f"(c[3])
        : "r"(a[0]), "r"(a[1]), "r"(a[2]), "r"(a[3]), "r"(b[0]), "r"(b[1]));
}
__device__ __forceinline__ float silu(float x) { return x / (1.0f + __expf(-x)); }

// ---------------------------------------------------------------------------
// Routing
// ---------------------------------------------------------------------------
__global__ void zero_counts_kernel() {
    if (threadIdx.x < E_EXP) d_cnt[threadIdx.x] = 0;
}
__global__ void route_kernel(const int* __restrict__ expert_ids) {
    int n = blockIdx.x * blockDim.x + threadIdx.x;
    if (n < N_ASG) {
        int e = expert_ids[n];
        int p = atomicAdd(&d_cnt[e], 1);
        d_slot[e * CAP + p] = n;
    }
}

// ---------------------------------------------------------------------------
// hidden f32 -> fp16 (RN), 8 elements per thread
// ---------------------------------------------------------------------------
__global__ __launch_bounds__(256)
void conv_x_kernel(const float* __restrict__ src) {
    size_t i = ((size_t)blockIdx.x * 256 + threadIdx.x) * 8;
    float4 v0 = *(const float4*)(src + i);
    float4 v1 = *(const float4*)(src + i + 4);
    __half2 h[4];
    h[0] = __floats2half2_rn(v0.x, v0.y);
    h[1] = __floats2half2_rn(v0.z, v0.w);
    h[2] = __floats2half2_rn(v1.x, v1.y);
    h[3] = __floats2half2_rn(v1.z, v1.w);
    *(uint4*)(d_xh + i) = *(uint4*)h;
}

// ---------------------------------------------------------------------------
// Transpose-convert: src f32 [e][KD][ND] -> dst fp16 [e][ND][KD]
// 64x64 tiles; e0 = expert chunk offset
// ---------------------------------------------------------------------------
template<int KD, int ND>
__global__ __launch_bounds__(256)
void transconv_kernel(const float* __restrict__ src, __half* __restrict__ dst, int e0) {
    __shared__ float tile[64][65];
    const int e = blockIdx.z + e0, kb = blockIdx.y, nb = blockIdx.x;
    const int t = threadIdx.x;
    const float* s = src + (size_t)e * KD * ND + (size_t)kb * 64 * ND + nb * 64;
#pragma unroll
    for (int j = 0; j < 4; j++) {
        int i = t + j * 256;                     // 0..1023 float4s
        int k_l = i >> 4, c4 = i & 15;           // 16 float4 per 64-col row
        float4 v = *(const float4*)(s + (size_t)k_l * ND + c4 * 4);
        tile[k_l][c4 * 4 + 0] = v.x;
        tile[k_l][c4 * 4 + 1] = v.y;
        tile[k_l][c4 * 4 + 2] = v.z;
        tile[k_l][c4 * 4 + 3] = v.w;
    }
    __syncthreads();
#pragma unroll
    for (int j = 0; j < 2; j++) {
        int i = t + j * 256;                     // 0..511 uint4 writes
        int n_l = i >> 3, kq = i & 7;            // 8 halves per write
        __half2 h[4];
#pragma unroll
        for (int q = 0; q < 4; q++)
            h[q] = __floats2half2_rn(tile[kq * 8 + 2 * q][n_l],
                                     tile[kq * 8 + 2 * q + 1][n_l]);
        __half* d = dst + ((size_t)e * ND + nb * 64 + n_l) * KD + kb * 64 + kq * 8;
        *(uint4*)d = *(uint4*)h;
    }
}

// ---------------------------------------------------------------------------
// fp16 mma GEMM, CTA 128x128, 8 warps 2Mx4N (64x32), K-stage 64.
// Single-barrier pipeline: wait -> sync -> issue(kt+2) -> math.
//   C[m][n] = sum_k A[m][k] * B[n][k]   (B stored n-major = W^T), expert e.
// e0 = expert chunk offset.
// GATHER/SILU=true : gemm1 — gathered A, silu, fp16 out (slot-ordered)
// GATHER/SILU=false: gemm2 — linear A, weighted fp16 scatter to d_yw[n]
// ---------------------------------------------------------------------------
template<int KG, int NG, bool GATHER, bool SILU>
__global__ __launch_bounds__(256, 2)
void hgemm_kernel(const __half* __restrict__ Aglob,
                  const __half* __restrict__ Bglob,
                  const float* __restrict__ ew,
                  __half* __restrict__ Out, int e0) {
    extern __shared__ __align__(16) __half sm[];
    __shared__ int   asg[128];
    __shared__ float wts[128];

    const int e  = blockIdx.z + e0;
    const int mt = blockIdx.y;                   // 0..3
    const int nt = blockIdx.x;
    const int tid = threadIdx.x;
    const int KT = KG / 64;

    if (tid < 128) {
        int n = d_slot[(e * 4 + mt) * 128 + tid];
        asg[tid] = n;
        if (!SILU) wts[tid] = ew[n];
    }
    __syncthreads();

    const __half* Abase = Aglob + (size_t)((e * 4 + mt) * 128) * KG;  // !GATHER
    const __half* Bbase = Bglob + ((size_t)e * NG + nt * 128) * KG;
    const uint32_t smb = smem_u32(sm);

    // stage issue: 4 A-chunks + 4 B-chunks of 16B per thread, XOR-swizzled
    auto issue = [&](int kt) {
        const int slot = kt % STAGES;
        const uint32_t sA = smb + slot * STAGE_BYTES;
        const uint32_t sB = sA + A_SM_BYTES;
#pragma unroll
        for (int j = 0; j < 4; j++) {
            int idx = tid + j * 256;             // 0..1023
            int row = idx >> 3, c = idx & 7;
            const __half* src = GATHER
                ? Aglob + (size_t)(asg[row] >> 1) * KG + kt * 64 + c * 8
                : Abase + (size_t)row * KG + kt * 64 + c * 8;
            cp16(sA + row * TILE_ROW_BYTES + ((c ^ (row & 7)) * 16), src);
        }
#pragma unroll
        for (int j = 0; j < 4; j++) {
            int idx = tid + j * 256;
            int row = idx >> 3, c = idx & 7;
            cp16(sB + row * TILE_ROW_BYTES + ((c ^ (row & 7)) * 16),
                 Bbase + (size_t)row * KG + kt * 64 + c * 8);
        }
    };

    const int wid  = tid >> 5, lane = tid & 31;
    const int g    = lane >> 2, tg = lane & 3;
    const int wm   = wid & 1;                    // 2 warps along M (64 each)
    const int wn   = wid >> 1;                   // 4 warps along N (32 each)

    // ldmatrix lane decomposition
    const int lt = lane >> 3, lr = lane & 7;

    // A x4: t0=(m-lo,k-lo) t1=(m-hi,k-lo) t2=(m-lo,k-hi) t3=(m-hi,k-hi)
    int a_row[4], a_xor[4];
#pragma unroll
    for (int ma = 0; ma < 4; ma++) {
        a_row[ma] = wm * 64 + ma * 16 + (lt & 1) * 8 + lr;
        a_xor[ma] = a_row[ma] & 7;
    }
    const int a_choff = lt >> 1;
    // B x4: t0=(n-lo,k-lo) t1=(n-lo,k-hi) t2=(n-hi,k-lo) t3=(n-hi,k-hi)
    int b_row[2], b_xor[2];
#pragma unroll
    for (int nb = 0; nb < 2; nb++) {
        b_row[nb] = wn * 32 + nb * 16 + (lt >> 1) * 8 + lr;
        b_xor[nb] = b_row[nb] & 7;
    }
    const int b_choff = lt & 1;

    float c[4][4][4];
#pragma unroll
    for (int i = 0; i < 4; i++)
#pragma unroll
        for (int j = 0; j < 4; j++)
#pragma unroll
            for (int k = 0; k < 4; k++) c[i][j][k] = 0.0f;

    issue(0); CP_COMMIT();
    issue(1); CP_COMMIT();

#pragma unroll 1
    for (int kt = 0; kt < KT; kt++) {
        CP_WAIT1();                              // group kt complete (this thread)
        __syncthreads();                         // all threads see stage kt; all done with kt-1
        if (kt + 2 < KT) issue(kt + 2);          // writes slot (kt-1)%3: safe post-barrier
        CP_COMMIT();

        const uint32_t sA = smb + (kt % STAGES) * STAGE_BYTES;
        const uint32_t sB = sA + A_SM_BYTES;

#pragma unroll
        for (int k16 = 0; k16 < 4; k16++) {
            uint32_t a[4][4], b[2][4];
#pragma unroll
            for (int ma = 0; ma < 4; ma++) {
                uint32_t addr = sA + a_row[ma] * TILE_ROW_BYTES
                              + (((2 * k16 + a_choff) ^ a_xor[ma]) << 4);
                ldsm_x4(a[ma], addr);
            }
#pragma unroll
            for (int nb = 0; nb < 2; nb++) {
                uint32_t addr = sB + b_row[nb] * TILE_ROW_BYTES
                              + (((2 * k16 + b_choff) ^ b_xor[nb]) << 4);
                ldsm_x4(b[nb], addr);
            }
#pragma unroll
            for (int ma = 0; ma < 4; ma++)
#pragma unroll
                for (int nb = 0; nb < 2; nb++) {
                    mma_f16(c[ma][2 * nb + 0], a[ma], &b[nb][0]);
                    mma_f16(c[ma][2 * nb + 1], a[ma], &b[nb][2]);
                }
        }
    }

    // epilogue
#pragma unroll
    for (int ma = 0; ma < 4; ma++) {
        int r0 = wm * 64 + ma * 16 + g;          // local rows r0, r0+8
        if (SILU) {
            size_t gr = (size_t)(e * 4 + mt) * 128 + r0;
#pragma unroll
            for (int na = 0; na < 4; na++) {
                int col = nt * 128 + wn * 32 + na * 8 + 2 * tg;
                __half2 v0 = __floats2half2_rn(silu(c[ma][na][0]), silu(c[ma][na][1]));
                __half2 v1 = __floats2half2_rn(silu(c[ma][na][2]), silu(c[ma][na][3]));
                *(__half2*)(Out + gr * NG + col)       = v0;
                *(__half2*)(Out + (gr + 8) * NG + col) = v1;
            }
        } else {
            // weighted fp16 scatter, assignment-indexed
            int   n0 = asg[r0],     n1 = asg[r0 + 8];
            float w0 = wts[r0],     w1 = wts[r0 + 8];
#pragma unroll
            for (int na = 0; na < 4; na++) {
                int col = nt * 128 + wn * 32 + na * 8 + 2 * tg;
                __half2 v0 = __floats2half2_rn(w0 * c[ma][na][0], w0 * c[ma][na][1]);
                __half2 v1 = __floats2half2_rn(w1 * c[ma][na][2], w1 * c[ma][na][3]);
                *(__half2*)(Out + (size_t)n0 * NG + col) = v0;
                *(__half2*)(Out + (size_t)n1 * NG + col) = v1;
            }
        }
    }
}

// ---------------------------------------------------------------------------
// Combine: out[t] = yw[2t] + yw[2t+1]  (fp16 in, f32 out, fully coalesced)
// ---------------------------------------------------------------------------
__global__ __launch_bounds__(256)
void combine_kernel(float* __restrict__ out) {
    int idx = blockIdx.x * 256 + threadIdx.x;    // one float4 of out; 2M total
    int t = idx >> 7, cc = idx & 127;            // cc: float4 index within row
    const __half2* y0 = (const __half2*)(d_yw + (size_t)(2 * t) * H_DIM + cc * 4);
    const __half2* y1 = (const __half2*)(d_yw + (size_t)(2 * t + 1) * H_DIM + cc * 4);
    uint2 p0 = *(const uint2*)y0;
    uint2 p1 = *(const uint2*)y1;
    float2 a0 = __half22float2(*(const __half2*)&p0.x);
    float2 a1 = __half22float2(*(const __half2*)&p0.y);
    float2 b0 = __half22float2(*(const __half2*)&p1.x);
    float2 b1 = __half22float2(*(const __half2*)&p1.y);
    float4 rr;
    rr.x = a0.x + b0.x;
    rr.y = a0.y + b0.y;
    rr.z = a1.x + b1.x;
    rr.w = a1.y + b1.y;
    ((float4*)out)[idx] = rr;
}

// ---------------------------------------------------------------------------
// Launch: chunked expert pipeline.
//   T stream: transconv W1 chunks 0..7, then W2 chunks 0..7 (events per chunk)
//   main:     zero+route+conv_x, then g1(c) gated on evW1[c],
//             then g2(c) gated on evW2[c], then combine.
// ---------------------------------------------------------------------------
extern "C" void kernel_launch(void* const* d_in, const int* in_sizes, int n_in,
                              void* d_out, int out_size) {
    const float* hidden = (const float*)d_in[0];   // [B, H]
    const float* ew     = (const float*)d_in[1];   // [B, K]
    const int*   ids    = (const int*)d_in[2];     // [B, K]
    const float* W1     = (const float*)d_in[3];   // [E, H, F]
    const float* W2     = (const float*)d_in[4];   // [E, F, H]
    float* out = (float*)d_out;

    static cudaStream_t sT = nullptr;
    static cudaEvent_t  evStart = nullptr;
    static cudaEvent_t  evW1[NCHUNK], evW2[NCHUNK];
    static bool inited = false;
    if (!inited) {
        cudaStreamCreateWithFlags(&sT, cudaStreamNonBlocking);
        cudaEventCreateWithFlags(&evStart, cudaEventDisableTiming);
        for (int c = 0; c < NCHUNK; c++) {
            cudaEventCreateWithFlags(&evW1[c], cudaEventDisableTiming);
            cudaEventCreateWithFlags(&evW2[c], cudaEventDisableTiming);
        }
        auto* k1i = hgemm_kernel<H_DIM, F_DIM, true, true>;
        auto* k2i = hgemm_kernel<F_DIM, H_DIM, false, false>;
        cudaFuncSetAttribute(k1i, cudaFuncAttributeMaxDynamicSharedMemorySize, DYN_SMEM);
        cudaFuncSetAttribute(k2i, cudaFuncAttributeMaxDynamicSharedMemorySize, DYN_SMEM);
        inited = true;
    }

    auto* k1 = hgemm_kernel<H_DIM, F_DIM, true, true>;
    auto* k2 = hgemm_kernel<F_DIM, H_DIM, false, false>;

    __half *xh, *w1h, *w2h, *hidh, *yw;
    cudaGetSymbolAddress((void**)&xh,  d_xh);
    cudaGetSymbolAddress((void**)&w1h, d_w1h);
    cudaGetSymbolAddress((void**)&w2h, d_w2h);
    cudaGetSymbolAddress((void**)&hidh, d_hidh);
    cudaGetSymbolAddress((void**)&yw,  d_yw);

    // Fork the transconv stream at capture start.
    cudaEventRecord(evStart, 0);
    cudaStreamWaitEvent(sT, evStart, 0);

    // T stream: all weight transpose-converts, chunked, W1 first.
    dim3 gt1(F_DIM / 64, H_DIM / 64, NE_CHUNK);
    for (int c = 0; c < NCHUNK; c++) {
        transconv_kernel<H_DIM, F_DIM><<<gt1, 256, 0, sT>>>(W1, w1h, c * NE_CHUNK);
        cudaEventRecord(evW1[c], sT);
    }
    dim3 gt2(H_DIM / 64, F_DIM / 64, NE_CHUNK);
    for (int c = 0; c < NCHUNK; c++) {
        transconv_kernel<F_DIM, H_DIM><<<gt2, 256, 0, sT>>>(W2, w2h, c * NE_CHUNK);
        cudaEventRecord(evW2[c], sT);
    }

    // Main stream: routing + x convert (GEMM1 prerequisites).
    zero_counts_kernel<<<1, 64>>>();
    route_kernel<<<(N_ASG + 255) / 256, 256>>>(ids);
    conv_x_kernel<<<(B_TOK * H_DIM) / (256 * 8), 256>>>(hidden);

    // GEMM1 chunks, each gated on its W1^T chunk.
    dim3 g1(F_DIM / 128, CAP / 128, NE_CHUNK);
    for (int c = 0; c < NCHUNK; c++) {
        cudaStreamWaitEvent(0, evW1[c], 0);
        k1<<<g1, 256, DYN_SMEM>>>(xh, w1h, nullptr, hidh, c * NE_CHUNK);
    }

    // GEMM2 chunks, each gated on its W2^T chunk.
    dim3 g2(H_DIM / 128, CAP / 128, NE_CHUNK);
    for (int c = 0; c < NCHUNK; c++) {
        cudaStreamWaitEvent(0, evW2[c], 0);
        k2<<<g2, 256, DYN_SMEM>>>(hidh, w2h, ew, yw, c * NE_CHUNK);
    }

    combine_kernel<<<(B_TOK * (H_DIM / 4)) / 256, 256>>>(out);
}

// round 12
// speedup vs baseline: 1.3561x; 1.3561x over previous
#include <cuda_runtime.h>
#include <cuda_fp16.h>
#include <cstdint>

// ---------------------------------------------------------------------------
// Problem constants
// ---------------------------------------------------------------------------
#define B_TOK 16384
#define K_TOP 2
#define E_EXP 64
#define H_DIM 512
#define F_DIM 1024
#define N_ASG 32768            // B*K assignments
#define CAP   512              // per-expert (balanced routing)

// GEMM tiling: CTA 128x128, 8 warps (2Mx4N, 64x32 each), K-stage 64, 3 stages
#define STAGES 3
#define TILE_ROW_BYTES 128                       // 64 halves, XOR-swizzled 16B chunks
#define A_SM_BYTES (128 * TILE_ROW_BYTES)        // 16384
#define STAGE_BYTES (2 * A_SM_BYTES)             // 32768 (A + B)
#define DYN_SMEM (STAGES * STAGE_BYTES)          // 98304 -> 2 CTAs/SM

// ---------------------------------------------------------------------------
// Scratch (device globals)
// ---------------------------------------------------------------------------
__device__ int    d_cnt[E_EXP];
__device__ int    d_slot[N_ASG];    // [e*CAP + p] = assignment n
__device__ __half d_xh [(size_t)B_TOK * H_DIM];          //  17 MB hidden fp16
__device__ __half d_w1h[(size_t)E_EXP * F_DIM * H_DIM];  //  67 MB W1^T  [e][f][h]
__device__ __half d_w2h[(size_t)E_EXP * H_DIM * F_DIM];  //  67 MB W2^T  [e][h][f]
__device__ __half d_hidh[(size_t)N_ASG * F_DIM];         //  67 MB silu(x@W1) fp16
__device__ __half d_yw [(size_t)N_ASG * H_DIM];          //  34 MB weighted outputs fp16, n-indexed

// ---------------------------------------------------------------------------
// PTX helpers (sm_80-vintage, base-sm_100 legal)
// ---------------------------------------------------------------------------
__device__ __forceinline__ uint32_t smem_u32(const void* p) {
    uint32_t a;
    asm("{ .reg .u64 t; cvta.to.shared.u64 t, %1; cvt.u32.u64 %0, t; }" : "=r"(a) : "l"(p));
    return a;
}
__device__ __forceinline__ void cp16(uint32_t dst, const void* src) {
    asm volatile("cp.async.cg.shared.global [%0], [%1], 16;" :: "r"(dst), "l"(src));
}
#define CP_COMMIT() asm volatile("cp.async.commit_group;" ::: "memory")
#define CP_WAIT1()  asm volatile("cp.async.wait_group 1;" ::: "memory")

__device__ __forceinline__ void ldsm_x4(uint32_t* r, uint32_t addr) {
    asm volatile("ldmatrix.sync.aligned.m8n8.x4.shared.b16 {%0,%1,%2,%3}, [%4];"
                 : "=r"(r[0]), "=r"(r[1]), "=r"(r[2]), "=r"(r[3]) : "r"(addr));
}
__device__ __forceinline__ void mma_f16(float* c, const uint32_t* a, const uint32_t* b) {
    asm volatile(
        "mma.sync.aligned.m16n8k16.row.col.f32.f16.f16.f32 "
        "{%0,%1,%2,%3}, {%4,%5,%6,%7}, {%8,%9}, {%0,%1,%2,%3};"
        : "+f"(c[0]), "+f"(c[1]), "+f"(c[2]), "+f"(c[3])
        : "r"(a[0]), "r"(a[1]), "r"(a[2]), "r"(a[3]), "r"(b[0]), "r"(b[1]));
}
__device__ __forceinline__ float silu(float x) { return x / (1.0f + __expf(-x)); }

// ---------------------------------------------------------------------------
// Routing
// ---------------------------------------------------------------------------
__global__ void zero_counts_kernel() {
    if (threadIdx.x < E_EXP) d_cnt[threadIdx.x] = 0;
}
__global__ void route_kernel(const int* __restrict__ expert_ids) {
    int n = blockIdx.x * blockDim.x + threadIdx.x;
    if (n < N_ASG) {
        int e = expert_ids[n];
        int p = atomicAdd(&d_cnt[e], 1);
        d_slot[e * CAP + p] = n;
    }
}

// ---------------------------------------------------------------------------
// hidden f32 -> fp16 (RN), 8 elements per thread
// ---------------------------------------------------------------------------
__global__ __launch_bounds__(256)
void conv_x_kernel(const float* __restrict__ src) {
    size_t i = ((size_t)blockIdx.x * 256 + threadIdx.x) * 8;
    float4 v0 = *(const float4*)(src + i);
    float4 v1 = *(const float4*)(src + i + 4);
    __half2 h[4];
    h[0] = __floats2half2_rn(v0.x, v0.y);
    h[1] = __floats2half2_rn(v0.z, v0.w);
    h[2] = __floats2half2_rn(v1.x, v1.y);
    h[3] = __floats2half2_rn(v1.z, v1.w);
    *(uint4*)(d_xh + i) = *(uint4*)h;
}

// ---------------------------------------------------------------------------
// Transpose-convert: src f32 [e][KD][ND] -> dst fp16 [e][ND][KD]
// 64x64 tiles, 256 threads: 4 float4 loads + 2 uint4 (8-half) writes per thread
// ---------------------------------------------------------------------------
template<int KD, int ND>
__global__ __launch_bounds__(256)
void transconv_kernel(const float* __restrict__ src, __half* __restrict__ dst) {
    __shared__ float tile[64][65];
    const int e = blockIdx.z, kb = blockIdx.y, nb = blockIdx.x;
    const int t = threadIdx.x;
    const float* s = src + (size_t)e * KD * ND + (size_t)kb * 64 * ND + nb * 64;
#pragma unroll
    for (int j = 0; j < 4; j++) {
        int i = t + j * 256;                     // 0..1023 float4s
        int k_l = i >> 4, c4 = i & 15;           // 16 float4 per 64-col row
        float4 v = *(const float4*)(s + (size_t)k_l * ND + c4 * 4);
        tile[k_l][c4 * 4 + 0] = v.x;
        tile[k_l][c4 * 4 + 1] = v.y;
        tile[k_l][c4 * 4 + 2] = v.z;
        tile[k_l][c4 * 4 + 3] = v.w;
    }
    __syncthreads();
#pragma unroll
    for (int j = 0; j < 2; j++) {
        int i = t + j * 256;                     // 0..511 uint4 writes
        int n_l = i >> 3, kq = i & 7;            // 8 halves per write
        __half2 h[4];
#pragma unroll
        for (int q = 0; q < 4; q++)
            h[q] = __floats2half2_rn(tile[kq * 8 + 2 * q][n_l],
                                     tile[kq * 8 + 2 * q + 1][n_l]);
        __half* d = dst + ((size_t)e * ND + nb * 64 + n_l) * KD + kb * 64 + kq * 8;
        *(uint4*)d = *(uint4*)h;
    }
}

// ---------------------------------------------------------------------------
// fp16 mma GEMM, CTA 128x128, 8 warps 2Mx4N (64x32), K-stage 64.
// Single-barrier pipeline: wait -> sync -> issue(kt+2) -> math.
//   C[m][n] = sum_k A[m][k] * B[n][k]   (B stored n-major = W^T), expert e.
// GATHER/SILU=true : gemm1 — gathered A, silu, fp16 out (slot-ordered)
// GATHER/SILU=false: gemm2 — linear A, weighted fp16 scatter to d_yw[n]
// ---------------------------------------------------------------------------
template<int KG, int NG, bool GATHER, bool SILU>
__global__ __launch_bounds__(256, 2)
void hgemm_kernel(const __half* __restrict__ Aglob,
                  const __half* __restrict__ Bglob,
                  const float* __restrict__ ew,
                  __half* __restrict__ Out) {
    extern __shared__ __align__(16) __half sm[];
    __shared__ int   asg[128];
    __shared__ float wts[128];

    const int e  = blockIdx.z;
    const int mt = blockIdx.y;                   // 0..3
    const int nt = blockIdx.x;
    const int tid = threadIdx.x;
    const int KT = KG / 64;

    if (tid < 128) {
        int n = d_slot[(e * 4 + mt) * 128 + tid];
        asg[tid] = n;
        if (!SILU) wts[tid] = ew[n];
    }
    __syncthreads();

    const __half* Abase = Aglob + (size_t)((e * 4 + mt) * 128) * KG;  // !GATHER
    const __half* Bbase = Bglob + ((size_t)e * NG + nt * 128) * KG;
    const uint32_t smb = smem_u32(sm);

    // stage issue: 4 A-chunks + 4 B-chunks of 16B per thread, XOR-swizzled
    auto issue = [&](int kt) {
        const int slot = kt % STAGES;
        const uint32_t sA = smb + slot * STAGE_BYTES;
        const uint32_t sB = sA + A_SM_BYTES;
#pragma unroll
        for (int j = 0; j < 4; j++) {
            int idx = tid + j * 256;             // 0..1023
            int row = idx >> 3, c = idx & 7;
            const __half* src = GATHER
                ? Aglob + (size_t)(asg[row] >> 1) * KG + kt * 64 + c * 8
                : Abase + (size_t)row * KG + kt * 64 + c * 8;
            cp16(sA + row * TILE_ROW_BYTES + ((c ^ (row & 7)) * 16), src);
        }
#pragma unroll
        for (int j = 0; j < 4; j++) {
            int idx = tid + j * 256;
            int row = idx >> 3, c = idx & 7;
            cp16(sB + row * TILE_ROW_BYTES + ((c ^ (row & 7)) * 16),
                 Bbase + (size_t)row * KG + kt * 64 + c * 8);
        }
    };

    const int wid  = tid >> 5, lane = tid & 31;
    const int g    = lane >> 2, tg = lane & 3;
    const int wm   = wid & 1;                    // 2 warps along M (64 each)
    const int wn   = wid >> 1;                   // 4 warps along N (32 each)

    // ldmatrix lane decomposition
    const int lt = lane >> 3, lr = lane & 7;

    // A x4: t0=(m-lo,k-lo) t1=(m-hi,k-lo) t2=(m-lo,k-hi) t3=(m-hi,k-hi)
    int a_row[4], a_xor[4];
#pragma unroll
    for (int ma = 0; ma < 4; ma++) {
        a_row[ma] = wm * 64 + ma * 16 + (lt & 1) * 8 + lr;
        a_xor[ma] = a_row[ma] & 7;
    }
    const int a_choff = lt >> 1;
    // B x4: t0=(n-lo,k-lo) t1=(n-lo,k-hi) t2=(n-hi,k-lo) t3=(n-hi,k-hi)
    int b_row[2], b_xor[2];
#pragma unroll
    for (int nb = 0; nb < 2; nb++) {
        b_row[nb] = wn * 32 + nb * 16 + (lt >> 1) * 8 + lr;
        b_xor[nb] = b_row[nb] & 7;
    }
    const int b_choff = lt & 1;

    float c[4][4][4];
#pragma unroll
    for (int i = 0; i < 4; i++)
#pragma unroll
        for (int j = 0; j < 4; j++)
#pragma unroll
            for (int k = 0; k < 4; k++) c[i][j][k] = 0.0f;

    issue(0); CP_COMMIT();
    issue(1); CP_COMMIT();

#pragma unroll 1
    for (int kt = 0; kt < KT; kt++) {
        CP_WAIT1();                              // group kt complete (this thread)
        __syncthreads();                         // all threads see stage kt; all done with kt-1
        if (kt + 2 < KT) issue(kt + 2);          // writes slot (kt-1)%3: safe post-barrier
        CP_COMMIT();

        const uint32_t sA = smb + (kt % STAGES) * STAGE_BYTES;
        const uint32_t sB = sA + A_SM_BYTES;

#pragma unroll
        for (int k16 = 0; k16 < 4; k16++) {
            uint32_t a[4][4], b[2][4];
#pragma unroll
            for (int ma = 0; ma < 4; ma++) {
                uint32_t addr = sA + a_row[ma] * TILE_ROW_BYTES
                              + (((2 * k16 + a_choff) ^ a_xor[ma]) << 4);
                ldsm_x4(a[ma], addr);
            }
#pragma unroll
            for (int nb = 0; nb < 2; nb++) {
                uint32_t addr = sB + b_row[nb] * TILE_ROW_BYTES
                              + (((2 * k16 + b_choff) ^ b_xor[nb]) << 4);
                ldsm_x4(b[nb], addr);
            }
#pragma unroll
            for (int ma = 0; ma < 4; ma++)
#pragma unroll
                for (int nb = 0; nb < 2; nb++) {
                    mma_f16(c[ma][2 * nb + 0], a[ma], &b[nb][0]);
                    mma_f16(c[ma][2 * nb + 1], a[ma], &b[nb][2]);
                }
        }
    }

    // epilogue
#pragma unroll
    for (int ma = 0; ma < 4; ma++) {
        int r0 = wm * 64 + ma * 16 + g;          // local rows r0, r0+8
        if (SILU) {
            size_t gr = (size_t)(e * 4 + mt) * 128 + r0;
#pragma unroll
            for (int na = 0; na < 4; na++) {
                int col = nt * 128 + wn * 32 + na * 8 + 2 * tg;
                __half2 v0 = __floats2half2_rn(silu(c[ma][na][0]), silu(c[ma][na][1]));
                __half2 v1 = __floats2half2_rn(silu(c[ma][na][2]), silu(c[ma][na][3]));
                *(__half2*)(Out + gr * NG + col)       = v0;
                *(__half2*)(Out + (gr + 8) * NG + col) = v1;
            }
        } else {
            // weighted fp16 scatter, assignment-indexed
            int   n0 = asg[r0],     n1 = asg[r0 + 8];
            float w0 = wts[r0],     w1 = wts[r0 + 8];
#pragma unroll
            for (int na = 0; na < 4; na++) {
                int col = nt * 128 + wn * 32 + na * 8 + 2 * tg;
                __half2 v0 = __floats2half2_rn(w0 * c[ma][na][0], w0 * c[ma][na][1]);
                __half2 v1 = __floats2half2_rn(w1 * c[ma][na][2], w1 * c[ma][na][3]);
                *(__half2*)(Out + (size_t)n0 * NG + col) = v0;
                *(__half2*)(Out + (size_t)n1 * NG + col) = v1;
            }
        }
    }
}

// ---------------------------------------------------------------------------
// Combine: out[t] = yw[2t] + yw[2t+1]  (fp16 in, f32 out, fully coalesced)
// ---------------------------------------------------------------------------
__global__ __launch_bounds__(256)
void combine_kernel(float* __restrict__ out) {
    int idx = blockIdx.x * 256 + threadIdx.x;    // one float4 of out; 2M total
    int t = idx >> 7, cc = idx & 127;            // cc: float4 index within row
    const __half2* y0 = (const __half2*)(d_yw + (size_t)(2 * t) * H_DIM + cc * 4);
    const __half2* y1 = (const __half2*)(d_yw + (size_t)(2 * t + 1) * H_DIM + cc * 4);
    uint2 p0 = *(const uint2*)y0;
    uint2 p1 = *(const uint2*)y1;
    float2 a0 = __half22float2(*(const __half2*)&p0.x);
    float2 a1 = __half22float2(*(const __half2*)&p0.y);
    float2 b0 = __half22float2(*(const __half2*)&p1.x);
    float2 b1 = __half22float2(*(const __half2*)&p1.y);
    float4 rr;
    rr.x = a0.x + b0.x;
    rr.y = a0.y + b0.y;
    rr.z = a1.x + b1.x;
    rr.w = a1.y + b1.y;
    ((float4*)out)[idx] = rr;
}

// ---------------------------------------------------------------------------
// Launch: R10 fork structure; conv_x moved off the critical path to s2.
//   s1: transconv(W2)            — joined before GEMM2
//   s2: zero + route + conv_x    — joined before GEMM1
//   s0: transconv(W1), GEMM1, GEMM2, combine
// ---------------------------------------------------------------------------
extern "C" void kernel_launch(void* const* d_in, const int* in_sizes, int n_in,
                              void* d_out, int out_size) {
    const float* hidden = (const float*)d_in[0];   // [B, H]
    const float* ew     = (const float*)d_in[1];   // [B, K]
    const int*   ids    = (const int*)d_in[2];     // [B, K]
    const float* W1     = (const float*)d_in[3];   // [E, H, F]
    const float* W2     = (const float*)d_in[4];   // [E, F, H]
    float* out = (float*)d_out;

    static cudaStream_t s1 = nullptr, s2 = nullptr;
    static cudaEvent_t  ev0 = nullptr, evW2 = nullptr, evR = nullptr;
    static bool inited = false;
    if (!inited) {
        cudaStreamCreateWithFlags(&s1, cudaStreamNonBlocking);
        cudaStreamCreateWithFlags(&s2, cudaStreamNonBlocking);
        cudaEventCreateWithFlags(&ev0,  cudaEventDisableTiming);
        cudaEventCreateWithFlags(&evW2, cudaEventDisableTiming);
        cudaEventCreateWithFlags(&evR,  cudaEventDisableTiming);
        auto* k1i = hgemm_kernel<H_DIM, F_DIM, true, true>;
        auto* k2i = hgemm_kernel<F_DIM, H_DIM, false, false>;
        cudaFuncSetAttribute(k1i, cudaFuncAttributeMaxDynamicSharedMemorySize, DYN_SMEM);
        cudaFuncSetAttribute(k2i, cudaFuncAttributeMaxDynamicSharedMemorySize, DYN_SMEM);
        inited = true;
    }

    auto* k1 = hgemm_kernel<H_DIM, F_DIM, true, true>;
    auto* k2 = hgemm_kernel<F_DIM, H_DIM, false, false>;

    __half *xh, *w1h, *w2h, *hidh, *yw;
    cudaGetSymbolAddress((void**)&xh,  d_xh);
    cudaGetSymbolAddress((void**)&w1h, d_w1h);
    cudaGetSymbolAddress((void**)&w2h, d_w2h);
    cudaGetSymbolAddress((void**)&hidh, d_hidh);
    cudaGetSymbolAddress((void**)&yw,  d_yw);

    // Fork side streams off the main stream.
    cudaEventRecord(ev0, 0);
    cudaStreamWaitEvent(s1, ev0, 0);
    cudaStreamWaitEvent(s2, ev0, 0);

    // s1: W2 transpose-convert (only needed by GEMM2; hidden under GEMM1)
    dim3 gt2(H_DIM / 64, F_DIM / 64, E_EXP);
    transconv_kernel<F_DIM, H_DIM><<<gt2, 256, 0, s1>>>(W2, w2h);
    cudaEventRecord(evW2, s1);

    // s2: routing + x convert (GEMM1 prerequisites; concurrent with W1^T)
    zero_counts_kernel<<<1, 64, 0, s2>>>();
    route_kernel<<<(N_ASG + 255) / 256, 256, 0, s2>>>(ids);
    conv_x_kernel<<<(B_TOK * H_DIM) / (256 * 8), 256, 0, s2>>>(hidden);
    cudaEventRecord(evR, s2);

    // main stream: W1 transpose-convert
    dim3 gt1(F_DIM / 64, H_DIM / 64, E_EXP);
    transconv_kernel<H_DIM, F_DIM><<<gt1, 256>>>(W1, w1h);

    // GEMM1 needs route results + xh
    cudaStreamWaitEvent(0, evR, 0);
    dim3 g1(F_DIM / 128, CAP / 128, E_EXP);    // (8, 4, 64)
    k1<<<g1, 256, DYN_SMEM>>>(xh, w1h, nullptr, hidh);

    // GEMM2 needs W2^T
    cudaStreamWaitEvent(0, evW2, 0);
    dim3 g2(H_DIM / 128, CAP / 128, E_EXP);    // (4, 4, 64)
    k2<<<g2, 256, DYN_SMEM>>>(hidh, w2h, ew, yw);

    combine_kernel<<<(B_TOK * (H_DIM / 4)) / 256, 256>>>(out);
}

// round 13
// speedup vs baseline: 1.3749x; 1.0139x over previous
#include <cuda_runtime.h>
#include <cuda_fp16.h>
#include <cstdint>

// ---------------------------------------------------------------------------
// Problem constants
// ---------------------------------------------------------------------------
#define B_TOK 16384
#define K_TOP 2
#define E_EXP 64
#define H_DIM 512
#define F_DIM 1024
#define N_ASG 32768            // B*K assignments
#define CAP   512              // per-expert (balanced routing)

// GEMM tiling: CTA 128x128, 8 warps (2Mx4N, 64x32 each), K-stage 64, 3 stages
#define STAGES 3
#define TILE_ROW_BYTES 128                       // 64 halves, XOR-swizzled 16B chunks
#define A_SM_BYTES (128 * TILE_ROW_BYTES)        // 16384
#define STAGE_BYTES (2 * A_SM_BYTES)             // 32768 (A + B)
#define DYN_SMEM (STAGES * STAGE_BYTES)          // 98304 -> 2 CTAs/SM

// ---------------------------------------------------------------------------
// Scratch (device globals)
// ---------------------------------------------------------------------------
__device__ int    d_cnt[E_EXP];
__device__ int    d_slot[N_ASG];    // [e*CAP + p] = assignment n
__device__ __half d_xh [(size_t)B_TOK * H_DIM];          //  17 MB hidden fp16
__device__ __half d_w1h[(size_t)E_EXP * F_DIM * H_DIM];  //  67 MB W1^T  [e][f][h]
__device__ __half d_w2h[(size_t)E_EXP * H_DIM * F_DIM];  //  67 MB W2^T  [e][h][f]
__device__ __half d_hidh[(size_t)N_ASG * F_DIM];         //  67 MB silu(x@W1) fp16
__device__ __half d_yw [(size_t)N_ASG * H_DIM];          //  34 MB weighted outputs fp16, n-indexed

// ---------------------------------------------------------------------------
// PTX helpers (sm_80-vintage, base-sm_100 legal)
// ---------------------------------------------------------------------------
__device__ __forceinline__ uint32_t smem_u32(const void* p) {
    uint32_t a;
    asm("{ .reg .u64 t; cvta.to.shared.u64 t, %1; cvt.u32.u64 %0, t; }" : "=r"(a) : "l"(p));
    return a;
}
__device__ __forceinline__ void cp16(uint32_t dst, const void* src) {
    asm volatile("cp.async.cg.shared.global [%0], [%1], 16;" :: "r"(dst), "l"(src));
}
#define CP_COMMIT() asm volatile("cp.async.commit_group;" ::: "memory")
#define CP_WAIT1()  asm volatile("cp.async.wait_group 1;" ::: "memory")

__device__ __forceinline__ void ldsm_x4(uint32_t* r, uint32_t addr) {
    asm volatile("ldmatrix.sync.aligned.m8n8.x4.shared.b16 {%0,%1,%2,%3}, [%4];"
                 : "=r"(r[0]), "=r"(r[1]), "=r"(r[2]), "=r"(r[3]) : "r"(addr));
}
__device__ __forceinline__ void mma_f16(float* c, const uint32_t* a, const uint32_t* b) {
    asm volatile(
        "mma.sync.aligned.m16n8k16.row.col.f32.f16.f16.f32 "
        "{%0,%1,%2,%3}, {%4,%5,%6,%7}, {%8,%9}, {%0,%1,%2,%3};"
        : "+f"(c[0]), "+f"(c[1]), "+f"(c[2]), "+f"(c[3])
        : "r"(a[0]), "r"(a[1]), "r"(a[2]), "r"(a[3]), "r"(b[0]), "r"(b[1]));
}
__device__ __forceinline__ float silu(float x) { return x / (1.0f + __expf(-x)); }

// ---------------------------------------------------------------------------
// Routing
// ---------------------------------------------------------------------------
__global__ void zero_counts_kernel() {
    if (threadIdx.x < E_EXP) d_cnt[threadIdx.x] = 0;
}
__global__ void route_kernel(const int* __restrict__ expert_ids) {
    int n = blockIdx.x * blockDim.x + threadIdx.x;
    if (n < N_ASG) {
        int e = expert_ids[n];
        int p = atomicAdd(&d_cnt[e], 1);
        d_slot[e * CAP + p] = n;
    }
}

// ---------------------------------------------------------------------------
// hidden f32 -> fp16 (RN), 8 elements per thread
// ---------------------------------------------------------------------------
__global__ __launch_bounds__(256)
void conv_x_kernel(const float* __restrict__ src) {
    size_t i = ((size_t)blockIdx.x * 256 + threadIdx.x) * 8;
    float4 v0 = *(const float4*)(src + i);
    float4 v1 = *(const float4*)(src + i + 4);
    __half2 h[4];
    h[0] = __floats2half2_rn(v0.x, v0.y);
    h[1] = __floats2half2_rn(v0.z, v0.w);
    h[2] = __floats2half2_rn(v1.x, v1.y);
    h[3] = __floats2half2_rn(v1.z, v1.w);
    *(uint4*)(d_xh + i) = *(uint4*)h;
}

// ---------------------------------------------------------------------------
// Transpose-convert: src f32 [e][KD][ND] -> dst fp16 [e][ND][KD]
// 64x64 tiles, 256 threads: 4 float4 loads + 2 uint4 (8-half) writes per thread
// ---------------------------------------------------------------------------
template<int KD, int ND>
__global__ __launch_bounds__(256)
void transconv_kernel(const float* __restrict__ src, __half* __restrict__ dst) {
    __shared__ float tile[64][65];
    const int e = blockIdx.z, kb = blockIdx.y, nb = blockIdx.x;
    const int t = threadIdx.x;
    const float* s = src + (size_t)e * KD * ND + (size_t)kb * 64 * ND + nb * 64;
#pragma unroll
    for (int j = 0; j < 4; j++) {
        int i = t + j * 256;                     // 0..1023 float4s
        int k_l = i >> 4, c4 = i & 15;           // 16 float4 per 64-col row
        float4 v = *(const float4*)(s + (size_t)k_l * ND + c4 * 4);
        tile[k_l][c4 * 4 + 0] = v.x;
        tile[k_l][c4 * 4 + 1] = v.y;
        tile[k_l][c4 * 4 + 2] = v.z;
        tile[k_l][c4 * 4 + 3] = v.w;
    }
    __syncthreads();
#pragma unroll
    for (int j = 0; j < 2; j++) {
        int i = t + j * 256;                     // 0..511 uint4 writes
        int n_l = i >> 3, kq = i & 7;            // 8 halves per write
        __half2 h[4];
#pragma unroll
        for (int q = 0; q < 4; q++)
            h[q] = __floats2half2_rn(tile[kq * 8 + 2 * q][n_l],
                                     tile[kq * 8 + 2 * q + 1][n_l]);
        __half* d = dst + ((size_t)e * ND + nb * 64 + n_l) * KD + kb * 64 + kq * 8;
        *(uint4*)d = *(uint4*)h;
    }
}

// ---------------------------------------------------------------------------
// fp16 mma GEMM, CTA 128x128, 8 warps 2Mx4N (64x32), K-stage 64.
// Single-barrier pipeline: wait -> sync -> issue(kt+2) -> math.
//   C[m][n] = sum_k A[m][k] * B[n][k]   (B stored n-major = W^T), expert e.
// GATHER/SILU=true : gemm1 — gathered A, silu, fp16 out (slot-ordered)
// GATHER/SILU=false: gemm2 — linear A, weighted fp16 scatter to d_yw[n]
// ---------------------------------------------------------------------------
template<int KG, int NG, bool GATHER, bool SILU>
__global__ __launch_bounds__(256, 2)
void hgemm_kernel(const __half* __restrict__ Aglob,
                  const __half* __restrict__ Bglob,
                  const float* __restrict__ ew,
                  __half* __restrict__ Out) {
    extern __shared__ __align__(16) __half sm[];
    __shared__ int   asg[128];
    __shared__ float wts[128];

    const int e  = blockIdx.z;
    const int mt = blockIdx.y;                   // 0..3
    const int nt = blockIdx.x;
    const int tid = threadIdx.x;
    const int KT = KG / 64;

    if (tid < 128) {
        int n = d_slot[(e * 4 + mt) * 128 + tid];
        asg[tid] = n;
        if (!SILU) wts[tid] = ew[n];
    }
    __syncthreads();

    const __half* Abase = Aglob + (size_t)((e * 4 + mt) * 128) * KG;  // !GATHER
    const __half* Bbase = Bglob + ((size_t)e * NG + nt * 128) * KG;
    const uint32_t smb = smem_u32(sm);

    // stage issue: 4 A-chunks + 4 B-chunks of 16B per thread, XOR-swizzled
    auto issue = [&](int kt) {
        const int slot = kt % STAGES;
        const uint32_t sA = smb + slot * STAGE_BYTES;
        const uint32_t sB = sA + A_SM_BYTES;
#pragma unroll
        for (int j = 0; j < 4; j++) {
            int idx = tid + j * 256;             // 0..1023
            int row = idx >> 3, c = idx & 7;
            const __half* src = GATHER
                ? Aglob + (size_t)(asg[row] >> 1) * KG + kt * 64 + c * 8
                : Abase + (size_t)row * KG + kt * 64 + c * 8;
            cp16(sA + row * TILE_ROW_BYTES + ((c ^ (row & 7)) * 16), src);
        }
#pragma unroll
        for (int j = 0; j < 4; j++) {
            int idx = tid + j * 256;
            int row = idx >> 3, c = idx & 7;
            cp16(sB + row * TILE_ROW_BYTES + ((c ^ (row & 7)) * 16),
                 Bbase + (size_t)row * KG + kt * 64 + c * 8);
        }
    };

    const int wid  = tid >> 5, lane = tid & 31;
    const int g    = lane >> 2, tg = lane & 3;
    const int wm   = wid & 1;                    // 2 warps along M (64 each)
    const int wn   = wid >> 1;                   // 4 warps along N (32 each)

    // ldmatrix lane decomposition
    const int lt = lane >> 3, lr = lane & 7;

    // A x4: t0=(m-lo,k-lo) t1=(m-hi,k-lo) t2=(m-lo,k-hi) t3=(m-hi,k-hi)
    int a_row[4], a_xor[4];
#pragma unroll
    for (int ma = 0; ma < 4; ma++) {
        a_row[ma] = wm * 64 + ma * 16 + (lt & 1) * 8 + lr;
        a_xor[ma] = a_row[ma] & 7;
    }
    const int a_choff = lt >> 1;
    // B x4: t0=(n-lo,k-lo) t1=(n-lo,k-hi) t2=(n-hi,k-lo) t3=(n-hi,k-hi)
    int b_row[2], b_xor[2];
#pragma unroll
    for (int nb = 0; nb < 2; nb++) {
        b_row[nb] = wn * 32 + nb * 16 + (lt >> 1) * 8 + lr;
        b_xor[nb] = b_row[nb] & 7;
    }
    const int b_choff = lt & 1;

    float c[4][4][4];
#pragma unroll
    for (int i = 0; i < 4; i++)
#pragma unroll
        for (int j = 0; j < 4; j++)
#pragma unroll
            for (int k = 0; k < 4; k++) c[i][j][k] = 0.0f;

    issue(0); CP_COMMIT();
    issue(1); CP_COMMIT();

#pragma unroll 1
    for (int kt = 0; kt < KT; kt++) {
        CP_WAIT1();                              // group kt complete (this thread)
        __syncthreads();                         // all threads see stage kt; all done with kt-1
        if (kt + 2 < KT) issue(kt + 2);          // writes slot (kt-1)%3: safe post-barrier
        CP_COMMIT();

        const uint32_t sA = smb + (kt % STAGES) * STAGE_BYTES;
        const uint32_t sB = sA + A_SM_BYTES;

#pragma unroll
        for (int k16 = 0; k16 < 4; k16++) {
            uint32_t a[4][4], b[2][4];
#pragma unroll
            for (int ma = 0; ma < 4; ma++) {
                uint32_t addr = sA + a_row[ma] * TILE_ROW_BYTES
                              + (((2 * k16 + a_choff) ^ a_xor[ma]) << 4);
                ldsm_x4(a[ma], addr);
            }
#pragma unroll
            for (int nb = 0; nb < 2; nb++) {
                uint32_t addr = sB + b_row[nb] * TILE_ROW_BYTES
                              + (((2 * k16 + b_choff) ^ b_xor[nb]) << 4);
                ldsm_x4(b[nb], addr);
            }
#pragma unroll
            for (int ma = 0; ma < 4; ma++)
#pragma unroll
                for (int nb = 0; nb < 2; nb++) {
                    mma_f16(c[ma][2 * nb + 0], a[ma], &b[nb][0]);
                    mma_f16(c[ma][2 * nb + 1], a[ma], &b[nb][2]);
                }
        }
    }

    // epilogue
#pragma unroll
    for (int ma = 0; ma < 4; ma++) {
        int r0 = wm * 64 + ma * 16 + g;          // local rows r0, r0+8
        if (SILU) {
            size_t gr = (size_t)(e * 4 + mt) * 128 + r0;
#pragma unroll
            for (int na = 0; na < 4; na++) {
                int col = nt * 128 + wn * 32 + na * 8 + 2 * tg;
                __half2 v0 = __floats2half2_rn(silu(c[ma][na][0]), silu(c[ma][na][1]));
                __half2 v1 = __floats2half2_rn(silu(c[ma][na][2]), silu(c[ma][na][3]));
                *(__half2*)(Out + gr * NG + col)       = v0;
                *(__half2*)(Out + (gr + 8) * NG + col) = v1;
            }
        } else {
            // weighted fp16 scatter, assignment-indexed
            int   n0 = asg[r0],     n1 = asg[r0 + 8];
            float w0 = wts[r0],     w1 = wts[r0 + 8];
#pragma unroll
            for (int na = 0; na < 4; na++) {
                int col = nt * 128 + wn * 32 + na * 8 + 2 * tg;
                __half2 v0 = __floats2half2_rn(w0 * c[ma][na][0], w0 * c[ma][na][1]);
                __half2 v1 = __floats2half2_rn(w1 * c[ma][na][2], w1 * c[ma][na][3]);
                *(__half2*)(Out + (size_t)n0 * NG + col) = v0;
                *(__half2*)(Out + (size_t)n1 * NG + col) = v1;
            }
        }
    }
}

// ---------------------------------------------------------------------------
// Combine: out[t] = yw[2t] + yw[2t+1]  (fp16 in, f32 out, fully coalesced)
// ---------------------------------------------------------------------------
__global__ __launch_bounds__(256)
void combine_kernel(float* __restrict__ out) {
    int idx = blockIdx.x * 256 + threadIdx.x;    // one float4 of out; 2M total
    int t = idx >> 7, cc = idx & 127;            // cc: float4 index within row
    const __half2* y0 = (const __half2*)(d_yw + (size_t)(2 * t) * H_DIM + cc * 4);
    const __half2* y1 = (const __half2*)(d_yw + (size_t)(2 * t + 1) * H_DIM + cc * 4);
    uint2 p0 = *(const uint2*)y0;
    uint2 p1 = *(const uint2*)y1;
    float2 a0 = __half22float2(*(const __half2*)&p0.x);
    float2 a1 = __half22float2(*(const __half2*)&p0.y);
    float2 b0 = __half22float2(*(const __half2*)&p1.x);
    float2 b1 = __half22float2(*(const __half2*)&p1.y);
    float4 rr;
    rr.x = a0.x + b0.x;
    rr.y = a0.y + b0.y;
    rr.z = a1.x + b1.x;
    rr.w = a1.y + b1.y;
    ((float4*)out)[idx] = rr;
}

// ---------------------------------------------------------------------------
// Launch: W2 transconv DELAYED until after W1 transconv (no t=0 bandwidth
// contention on the critical path); W2 then overlaps GEMM1 on s1.
//   s1: (wait evW1) transconv(W2)        — joined before GEMM2
//   s2: zero + route + conv_x            — joined before GEMM1
//   s0: transconv(W1) [evW1], GEMM1, GEMM2, combine
// ---------------------------------------------------------------------------
extern "C" void kernel_launch(void* const* d_in, const int* in_sizes, int n_in,
                              void* d_out, int out_size) {
    const float* hidden = (const float*)d_in[0];   // [B, H]
    const float* ew     = (const float*)d_in[1];   // [B, K]
    const int*   ids    = (const int*)d_in[2];     // [B, K]
    const float* W1     = (const float*)d_in[3];   // [E, H, F]
    const float* W2     = (const float*)d_in[4];   // [E, F, H]
    float* out = (float*)d_out;

    static cudaStream_t s1 = nullptr, s2 = nullptr;
    static cudaEvent_t  ev0 = nullptr, evW1 = nullptr, evW2 = nullptr, evR = nullptr;
    static bool inited = false;
    if (!inited) {
        cudaStreamCreateWithFlags(&s1, cudaStreamNonBlocking);
        cudaStreamCreateWithFlags(&s2, cudaStreamNonBlocking);
        cudaEventCreateWithFlags(&ev0,  cudaEventDisableTiming);
        cudaEventCreateWithFlags(&evW1, cudaEventDisableTiming);
        cudaEventCreateWithFlags(&evW2, cudaEventDisableTiming);
        cudaEventCreateWithFlags(&evR,  cudaEventDisableTiming);
        auto* k1i = hgemm_kernel<H_DIM, F_DIM, true, true>;
        auto* k2i = hgemm_kernel<F_DIM, H_DIM, false, false>;
        cudaFuncSetAttribute(k1i, cudaFuncAttributeMaxDynamicSharedMemorySize, DYN_SMEM);
        cudaFuncSetAttribute(k2i, cudaFuncAttributeMaxDynamicSharedMemorySize, DYN_SMEM);
        inited = true;
    }

    auto* k1 = hgemm_kernel<H_DIM, F_DIM, true, true>;
    auto* k2 = hgemm_kernel<F_DIM, H_DIM, false, false>;

    __half *xh, *w1h, *w2h, *hidh, *yw;
    cudaGetSymbolAddress((void**)&xh,  d_xh);
    cudaGetSymbolAddress((void**)&w1h, d_w1h);
    cudaGetSymbolAddress((void**)&w2h, d_w2h);
    cudaGetSymbolAddress((void**)&hidh, d_hidh);
    cudaGetSymbolAddress((void**)&yw,  d_yw);

    // Fork side streams off the main stream.
    cudaEventRecord(ev0, 0);
    cudaStreamWaitEvent(s1, ev0, 0);
    cudaStreamWaitEvent(s2, ev0, 0);

    // s2: routing + x convert (GEMM1 prerequisites; concurrent with W1^T)
    zero_counts_kernel<<<1, 64, 0, s2>>>();
    route_kernel<<<(N_ASG + 255) / 256, 256, 0, s2>>>(ids);
    conv_x_kernel<<<(B_TOK * H_DIM) / (256 * 8), 256, 0, s2>>>(hidden);
    cudaEventRecord(evR, s2);

    // main stream: W1 transpose-convert (full bandwidth — critical path)
    dim3 gt1(F_DIM / 64, H_DIM / 64, E_EXP);
    transconv_kernel<H_DIM, F_DIM><<<gt1, 256>>>(W1, w1h);
    cudaEventRecord(evW1, 0);

    // s1: W2 transpose-convert AFTER W1 — runs in GEMM1's shadow
    cudaStreamWaitEvent(s1, evW1, 0);
    dim3 gt2(H_DIM / 64, F_DIM / 64, E_EXP);
    transconv_kernel<F_DIM, H_DIM><<<gt2, 256, 0, s1>>>(W2, w2h);
    cudaEventRecord(evW2, s1);

    // GEMM1 needs route results + xh (+ W1^T, already ordered on main stream)
    cudaStreamWaitEvent(0, evR, 0);
    dim3 g1(F_DIM / 128, CAP / 128, E_EXP);    // (8, 4, 64)
    k1<<<g1, 256, DYN_SMEM>>>(xh, w1h, nullptr, hidh);

    // GEMM2 needs W2^T
    cudaStreamWaitEvent(0, evW2, 0);
    dim3 g2(H_DIM / 128, CAP / 128, E_EXP);    // (4, 4, 64)
    k2<<<g2, 256, DYN_SMEM>>>(hidh, w2h, ew, yw);

    combine_kernel<<<(B_TOK * (H_DIM / 4)) / 256, 256>>>(out);
}

// round 14
// speedup vs baseline: 1.3830x; 1.0059x over previous
#include <cuda_runtime.h>
#include <cuda_fp16.h>
#include <cstdint>

// ---------------------------------------------------------------------------
// Problem constants
// ---------------------------------------------------------------------------
#define B_TOK 16384
#define K_TOP 2
#define E_EXP 64
#define H_DIM 512
#define F_DIM 1024
#define N_ASG 32768            // B*K assignments
#define CAP   512              // per-expert (balanced routing)
#define EHALF (E_EXP / 2)      // 32 experts per GEMM1 chunk

// GEMM tiling: CTA 128x128, 8 warps (2Mx4N, 64x32 each), K-stage 64, 3 stages
#define STAGES 3
#define TILE_ROW_BYTES 128                       // 64 halves, XOR-swizzled 16B chunks
#define A_SM_BYTES (128 * TILE_ROW_BYTES)        // 16384
#define STAGE_BYTES (2 * A_SM_BYTES)             // 32768 (A + B)
#define DYN_SMEM (STAGES * STAGE_BYTES)          // 98304 -> 2 CTAs/SM

// ---------------------------------------------------------------------------
// Scratch (device globals)
// ---------------------------------------------------------------------------
__device__ int    d_cnt[E_EXP];
__device__ int    d_slot[N_ASG];    // [e*CAP + p] = assignment n
__device__ __half d_xh [(size_t)B_TOK * H_DIM];          //  17 MB hidden fp16
__device__ __half d_w1h[(size_t)E_EXP * F_DIM * H_DIM];  //  67 MB W1^T  [e][f][h]
__device__ __half d_w2h[(size_t)E_EXP * H_DIM * F_DIM];  //  67 MB W2^T  [e][h][f]
__device__ __half d_hidh[(size_t)N_ASG * F_DIM];         //  67 MB silu(x@W1) fp16
__device__ __half d_yw [(size_t)N_ASG * H_DIM];          //  34 MB weighted outputs fp16, n-indexed

// ---------------------------------------------------------------------------
// PTX helpers (sm_80-vintage, base-sm_100 legal)
// ---------------------------------------------------------------------------
__device__ __forceinline__ uint32_t smem_u32(const void* p) {
    uint32_t a;
    asm("{ .reg .u64 t; cvta.to.shared.u64 t, %1; cvt.u32.u64 %0, t; }" : "=r"(a) : "l"(p));
    return a;
}
__device__ __forceinline__ void cp16(uint32_t dst, const void* src) {
    asm volatile("cp.async.cg.shared.global [%0], [%1], 16;" :: "r"(dst), "l"(src));
}
#define CP_COMMIT() asm volatile("cp.async.commit_group;" ::: "memory")
#define CP_WAIT1()  asm volatile("cp.async.wait_group 1;" ::: "memory")

__device__ __forceinline__ void ldsm_x4(uint32_t* r, uint32_t addr) {
    asm volatile("ldmatrix.sync.aligned.m8n8.x4.shared.b16 {%0,%1,%2,%3}, [%4];"
                 : "=r"(r[0]), "=r"(r[1]), "=r"(r[2]), "=r"(r[3]) : "r"(addr));
}
__device__ __forceinline__ void mma_f16(float* c, const uint32_t* a, const uint32_t* b) {
    asm volatile(
        "mma.sync.aligned.m16n8k16.row.col.f32.f16.f16.f32 "
        "{%0,%1,%2,%3}, {%4,%5,%6,%7}, {%8,%9}, {%0,%1,%2,%3};"
        : "+f"(c[0]), "+f"(c[1]), "+f"(c[2]), "+f"(c[3])
        : "r"(a[0]), "r"(a[1]), "r"(a[2]), "r"(a[3]), "r"(b[0]), "r"(b[1]));
}
__device__ __forceinline__ float silu(float x) { return x / (1.0f + __expf(-x)); }

// ---------------------------------------------------------------------------
// Routing
// ---------------------------------------------------------------------------
__global__ void zero_counts_kernel() {
    if (threadIdx.x < E_EXP) d_cnt[threadIdx.x] = 0;
}
__global__ void route_kernel(const int* __restrict__ expert_ids) {
    int n = blockIdx.x * blockDim.x + threadIdx.x;
    if (n < N_ASG) {
        int e = expert_ids[n];
        int p = atomicAdd(&d_cnt[e], 1);
        d_slot[e * CAP + p] = n;
    }
}

// ---------------------------------------------------------------------------
// hidden f32 -> fp16 (RN), 8 elements per thread
// ---------------------------------------------------------------------------
__global__ __launch_bounds__(256)
void conv_x_kernel(const float* __restrict__ src) {
    size_t i = ((size_t)blockIdx.x * 256 + threadIdx.x) * 8;
    float4 v0 = *(const float4*)(src + i);
    float4 v1 = *(const float4*)(src + i + 4);
    __half2 h[4];
    h[0] = __floats2half2_rn(v0.x, v0.y);
    h[1] = __floats2half2_rn(v0.z, v0.w);
    h[2] = __floats2half2_rn(v1.x, v1.y);
    h[3] = __floats2half2_rn(v1.z, v1.w);
    *(uint4*)(d_xh + i) = *(uint4*)h;
}

// ---------------------------------------------------------------------------
// Transpose-convert: src f32 [e][KD][ND] -> dst fp16 [e][ND][KD]
// 64x64 tiles; e0 = expert offset for chunked launches
// ---------------------------------------------------------------------------
template<int KD, int ND>
__global__ __launch_bounds__(256)
void transconv_kernel(const float* __restrict__ src, __half* __restrict__ dst, int e0) {
    __shared__ float tile[64][65];
    const int e = blockIdx.z + e0, kb = blockIdx.y, nb = blockIdx.x;
    const int t = threadIdx.x;
    const float* s = src + (size_t)e * KD * ND + (size_t)kb * 64 * ND + nb * 64;
#pragma unroll
    for (int j = 0; j < 4; j++) {
        int i = t + j * 256;                     // 0..1023 float4s
        int k_l = i >> 4, c4 = i & 15;           // 16 float4 per 64-col row
        float4 v = *(const float4*)(s + (size_t)k_l * ND + c4 * 4);
        tile[k_l][c4 * 4 + 0] = v.x;
        tile[k_l][c4 * 4 + 1] = v.y;
        tile[k_l][c4 * 4 + 2] = v.z;
        tile[k_l][c4 * 4 + 3] = v.w;
    }
    __syncthreads();
#pragma unroll
    for (int j = 0; j < 2; j++) {
        int i = t + j * 256;                     // 0..511 uint4 writes
        int n_l = i >> 3, kq = i & 7;            // 8 halves per write
        __half2 h[4];
#pragma unroll
        for (int q = 0; q < 4; q++)
            h[q] = __floats2half2_rn(tile[kq * 8 + 2 * q][n_l],
                                     tile[kq * 8 + 2 * q + 1][n_l]);
        __half* d = dst + ((size_t)e * ND + nb * 64 + n_l) * KD + kb * 64 + kq * 8;
        *(uint4*)d = *(uint4*)h;
    }
}

// ---------------------------------------------------------------------------
// fp16 mma GEMM, CTA 128x128, 8 warps 2Mx4N (64x32), K-stage 64.
// Single-barrier pipeline: wait -> sync -> issue(kt+2) -> math.
//   C[m][n] = sum_k A[m][k] * B[n][k]   (B stored n-major = W^T), expert e+e0.
// GATHER/SILU=true : gemm1 — gathered A, silu, fp16 out (slot-ordered)
// GATHER/SILU=false: gemm2 — linear A, weighted fp16 scatter to d_yw[n]
// ---------------------------------------------------------------------------
template<int KG, int NG, bool GATHER, bool SILU>
__global__ __launch_bounds__(256, 2)
void hgemm_kernel(const __half* __restrict__ Aglob,
                  const __half* __restrict__ Bglob,
                  const float* __restrict__ ew,
                  __half* __restrict__ Out, int e0) {
    extern __shared__ __align__(16) __half sm[];
    __shared__ int   asg[128];
    __shared__ float wts[128];

    const int e  = blockIdx.z + e0;
    const int mt = blockIdx.y;                   // 0..3
    const int nt = blockIdx.x;
    const int tid = threadIdx.x;
    const int KT = KG / 64;

    if (tid < 128) {
        int n = d_slot[(e * 4 + mt) * 128 + tid];
        asg[tid] = n;
        if (!SILU) wts[tid] = ew[n];
    }
    __syncthreads();

    const __half* Abase = Aglob + (size_t)((e * 4 + mt) * 128) * KG;  // !GATHER
    const __half* Bbase = Bglob + ((size_t)e * NG + nt * 128) * KG;
    const uint32_t smb = smem_u32(sm);

    // stage issue: 4 A-chunks + 4 B-chunks of 16B per thread, XOR-swizzled
    auto issue = [&](int kt) {
        const int slot = kt % STAGES;
        const uint32_t sA = smb + slot * STAGE_BYTES;
        const uint32_t sB = sA + A_SM_BYTES;
#pragma unroll
        for (int j = 0; j < 4; j++) {
            int idx = tid + j * 256;             // 0..1023
            int row = idx >> 3, c = idx & 7;
            const __half* src = GATHER
                ? Aglob + (size_t)(asg[row] >> 1) * KG + kt * 64 + c * 8
                : Abase + (size_t)row * KG + kt * 64 + c * 8;
            cp16(sA + row * TILE_ROW_BYTES + ((c ^ (row & 7)) * 16), src);
        }
#pragma unroll
        for (int j = 0; j < 4; j++) {
            int idx = tid + j * 256;
            int row = idx >> 3, c = idx & 7;
            cp16(sB + row * TILE_ROW_BYTES + ((c ^ (row & 7)) * 16),
                 Bbase + (size_t)row * KG + kt * 64 + c * 8);
        }
    };

    const int wid  = tid >> 5, lane = tid & 31;
    const int g    = lane >> 2, tg = lane & 3;
    const int wm   = wid & 1;                    // 2 warps along M (64 each)
    const int wn   = wid >> 1;                   // 4 warps along N (32 each)

    // ldmatrix lane decomposition
    const int lt = lane >> 3, lr = lane & 7;

    // A x4: t0=(m-lo,k-lo) t1=(m-hi,k-lo) t2=(m-lo,k-hi) t3=(m-hi,k-hi)
    int a_row[4], a_xor[4];
#pragma unroll
    for (int ma = 0; ma < 4; ma++) {
        a_row[ma] = wm * 64 + ma * 16 + (lt & 1) * 8 + lr;
        a_xor[ma] = a_row[ma] & 7;
    }
    const int a_choff = lt >> 1;
    // B x4: t0=(n-lo,k-lo) t1=(n-lo,k-hi) t2=(n-hi,k-lo) t3=(n-hi,k-hi)
    int b_row[2], b_xor[2];
#pragma unroll
    for (int nb = 0; nb < 2; nb++) {
        b_row[nb] = wn * 32 + nb * 16 + (lt >> 1) * 8 + lr;
        b_xor[nb] = b_row[nb] & 7;
    }
    const int b_choff = lt & 1;

    float c[4][4][4];
#pragma unroll
    for (int i = 0; i < 4; i++)
#pragma unroll
        for (int j = 0; j < 4; j++)
#pragma unroll
            for (int k = 0; k < 4; k++) c[i][j][k] = 0.0f;

    issue(0); CP_COMMIT();
    issue(1); CP_COMMIT();

#pragma unroll 1
    for (int kt = 0; kt < KT; kt++) {
        CP_WAIT1();                              // group kt complete (this thread)
        __syncthreads();                         // all threads see stage kt; all done with kt-1
        if (kt + 2 < KT) issue(kt + 2);          // writes slot (kt-1)%3: safe post-barrier
        CP_COMMIT();

        const uint32_t sA = smb + (kt % STAGES) * STAGE_BYTES;
        const uint32_t sB = sA + A_SM_BYTES;

#pragma unroll
        for (int k16 = 0; k16 < 4; k16++) {
            uint32_t a[4][4], b[2][4];
#pragma unroll
            for (int ma = 0; ma < 4; ma++) {
                uint32_t addr = sA + a_row[ma] * TILE_ROW_BYTES
                              + (((2 * k16 + a_choff) ^ a_xor[ma]) << 4);
                ldsm_x4(a[ma], addr);
            }
#pragma unroll
            for (int nb = 0; nb < 2; nb++) {
                uint32_t addr = sB + b_row[nb] * TILE_ROW_BYTES
                              + (((2 * k16 + b_choff) ^ b_xor[nb]) << 4);
                ldsm_x4(b[nb], addr);
            }
#pragma unroll
            for (int ma = 0; ma < 4; ma++)
#pragma unroll
                for (int nb = 0; nb < 2; nb++) {
                    mma_f16(c[ma][2 * nb + 0], a[ma], &b[nb][0]);
                    mma_f16(c[ma][2 * nb + 1], a[ma], &b[nb][2]);
                }
        }
    }

    // epilogue
#pragma unroll
    for (int ma = 0; ma < 4; ma++) {
        int r0 = wm * 64 + ma * 16 + g;          // local rows r0, r0+8
        if (SILU) {
            size_t gr = (size_t)(e * 4 + mt) * 128 + r0;
#pragma unroll
            for (int na = 0; na < 4; na++) {
                int col = nt * 128 + wn * 32 + na * 8 + 2 * tg;
                __half2 v0 = __floats2half2_rn(silu(c[ma][na][0]), silu(c[ma][na][1]));
                __half2 v1 = __floats2half2_rn(silu(c[ma][na][2]), silu(c[ma][na][3]));
                *(__half2*)(Out + gr * NG + col)       = v0;
                *(__half2*)(Out + (gr + 8) * NG + col) = v1;
            }
        } else {
            // weighted fp16 scatter, assignment-indexed
            int   n0 = asg[r0],     n1 = asg[r0 + 8];
            float w0 = wts[r0],     w1 = wts[r0 + 8];
#pragma unroll
            for (int na = 0; na < 4; na++) {
                int col = nt * 128 + wn * 32 + na * 8 + 2 * tg;
                __half2 v0 = __floats2half2_rn(w0 * c[ma][na][0], w0 * c[ma][na][1]);
                __half2 v1 = __floats2half2_rn(w1 * c[ma][na][2], w1 * c[ma][na][3]);
                *(__half2*)(Out + (size_t)n0 * NG + col) = v0;
                *(__half2*)(Out + (size_t)n1 * NG + col) = v1;
            }
        }
    }
}

// ---------------------------------------------------------------------------
// Combine: out[t] = yw[2t] + yw[2t+1]  (fp16 in, f32 out, fully coalesced)
// ---------------------------------------------------------------------------
__global__ __launch_bounds__(256)
void combine_kernel(float* __restrict__ out) {
    int idx = blockIdx.x * 256 + threadIdx.x;    // one float4 of out; 2M total
    int t = idx >> 7, cc = idx & 127;            // cc: float4 index within row
    const __half2* y0 = (const __half2*)(d_yw + (size_t)(2 * t) * H_DIM + cc * 4);
    const __half2* y1 = (const __half2*)(d_yw + (size_t)(2 * t + 1) * H_DIM + cc * 4);
    uint2 p0 = *(const uint2*)y0;
    uint2 p1 = *(const uint2*)y1;
    float2 a0 = __half22float2(*(const __half2*)&p0.x);
    float2 a1 = __half22float2(*(const __half2*)&p0.y);
    float2 b0 = __half22float2(*(const __half2*)&p1.x);
    float2 b1 = __half22float2(*(const __half2*)&p1.y);
    float4 rr;
    rr.x = a0.x + b0.x;
    rr.y = a0.y + b0.y;
    rr.z = a1.x + b1.x;
    rr.w = a1.y + b1.y;
    ((float4*)out)[idx] = rr;
}

// ---------------------------------------------------------------------------
// Launch: 2-chunk W1T + GEMM1 pipeline.
//   s2: zero + route + conv_x                      [evR]
//   s0: W1Ta (e0-31) [evW1a], (wait evR) k1a,
//       (wait evW1b) k1b, (wait evW2) k2, combine
//   s1: (wait evW1a) W1Tb (e32-63) [evW1b], W2T [evW2]
// ---------------------------------------------------------------------------
extern "C" void kernel_launch(void* const* d_in, const int* in_sizes, int n_in,
                              void* d_out, int out_size) {
    const float* hidden = (const float*)d_in[0];   // [B, H]
    const float* ew     = (const float*)d_in[1];   // [B, K]
    const int*   ids    = (const int*)d_in[2];     // [B, K]
    const float* W1     = (const float*)d_in[3];   // [E, H, F]
    const float* W2     = (const float*)d_in[4];   // [E, F, H]
    float* out = (float*)d_out;

    static cudaStream_t s1 = nullptr, s2 = nullptr;
    static cudaEvent_t  ev0 = nullptr, evW1a = nullptr, evW1b = nullptr,
                        evW2 = nullptr, evR = nullptr;
    static bool inited = false;
    if (!inited) {
        cudaStreamCreateWithFlags(&s1, cudaStreamNonBlocking);
        cudaStreamCreateWithFlags(&s2, cudaStreamNonBlocking);
        cudaEventCreateWithFlags(&ev0,   cudaEventDisableTiming);
        cudaEventCreateWithFlags(&evW1a, cudaEventDisableTiming);
        cudaEventCreateWithFlags(&evW1b, cudaEventDisableTiming);
        cudaEventCreateWithFlags(&evW2,  cudaEventDisableTiming);
        cudaEventCreateWithFlags(&evR,   cudaEventDisableTiming);
        auto* k1i = hgemm_kernel<H_DIM, F_DIM, true, true>;
        auto* k2i = hgemm_kernel<F_DIM, H_DIM, false, false>;
        cudaFuncSetAttribute(k1i, cudaFuncAttributeMaxDynamicSharedMemorySize, DYN_SMEM);
        cudaFuncSetAttribute(k2i, cudaFuncAttributeMaxDynamicSharedMemorySize, DYN_SMEM);
        inited = true;
    }

    auto* k1 = hgemm_kernel<H_DIM, F_DIM, true, true>;
    auto* k2 = hgemm_kernel<F_DIM, H_DIM, false, false>;

    __half *xh, *w1h, *w2h, *hidh, *yw;
    cudaGetSymbolAddress((void**)&xh,  d_xh);
    cudaGetSymbolAddress((void**)&w1h, d_w1h);
    cudaGetSymbolAddress((void**)&w2h, d_w2h);
    cudaGetSymbolAddress((void**)&hidh, d_hidh);
    cudaGetSymbolAddress((void**)&yw,  d_yw);

    // Fork side streams off the main stream.
    cudaEventRecord(ev0, 0);
    cudaStreamWaitEvent(s1, ev0, 0);
    cudaStreamWaitEvent(s2, ev0, 0);

    // s2: routing + x convert (GEMM1 prerequisites)
    zero_counts_kernel<<<1, 64, 0, s2>>>();
    route_kernel<<<(N_ASG + 255) / 256, 256, 0, s2>>>(ids);
    conv_x_kernel<<<(B_TOK * H_DIM) / (256 * 8), 256, 0, s2>>>(hidden);
    cudaEventRecord(evR, s2);

    // main: W1^T first half (full bandwidth — critical path)
    dim3 gt1(F_DIM / 64, H_DIM / 64, EHALF);
    transconv_kernel<H_DIM, F_DIM><<<gt1, 256>>>(W1, w1h, 0);
    cudaEventRecord(evW1a, 0);

    // s1: W1^T second half after first (runs under k1a), then W2^T (under k1b/k2)
    cudaStreamWaitEvent(s1, evW1a, 0);
    transconv_kernel<H_DIM, F_DIM><<<gt1, 256, 0, s1>>>(W1, w1h, EHALF);
    cudaEventRecord(evW1b, s1);
    dim3 gt2(H_DIM / 64, F_DIM / 64, E_EXP);
    transconv_kernel<F_DIM, H_DIM><<<gt2, 256, 0, s1>>>(W2, w2h, 0);
    cudaEventRecord(evW2, s1);

    // GEMM1 chunk a (e 0-31): needs route + xh + W1^T[0:32]
    cudaStreamWaitEvent(0, evR, 0);
    dim3 g1(F_DIM / 128, CAP / 128, EHALF);    // (8, 4, 32)
    k1<<<g1, 256, DYN_SMEM>>>(xh, w1h, nullptr, hidh, 0);

    // GEMM1 chunk b (e 32-63): CTAs backfill chunk a's tail wave
    cudaStreamWaitEvent(0, evW1b, 0);
    k1<<<g1, 256, DYN_SMEM>>>(xh, w1h, nullptr, hidh, EHALF);

    // GEMM2: needs full W2^T + GEMM1 (stream-ordered)
    cudaStreamWaitEvent(0, evW2, 0);
    dim3 g2(H_DIM / 128, CAP / 128, E_EXP);    // (4, 4, 64)
    k2<<<g2, 256, DYN_SMEM>>>(hidh, w2h, ew, yw, 0);

    combine_kernel<<<(B_TOK * (H_DIM / 4)) / 256, 256>>>(out);
}